// round 13
// baseline (speedup 1.0000x reference)
#include <cuda_runtime.h>
#include <cuda_fp16.h>
#include <stdint.h>

#define NH 3
#define NB 16
#define NN 1024
#define NF 512
#define NFP 1024

// ---------------------------------------------------------------------------
// Scratch arena
// ---------------------------------------------------------------------------
#define OFF_XT    0ull            // x^T fp16 [b][f][n]        16 MB
#define OFF_KTH   16777216ull     // kernels^T fp16 [h][fp][f]  3 MB
#define OFF_Y     19922944ull     // y fp16 [hb][n][f]         48 MB
#define OFF_AH    70254592ull     // attn fp16 [hb][n][j]      96 MB
#define OFF_W2S   170917888ull
#define OFF_W2N   170924032ull
#define OFF_SS    170930176ull
#define OFF_SN    171126784ull
#define OFF_BM    171323392ull
#define OFF_E1    171327488ull    // e^{c-M} fp32 [hb][j]
#define OFF_E2    171524096ull    // e^{0.2(c-M)} fp32 [hb][j]
#define OFF_M     171720704ull    // per-hb max c (48 floats)
#define ARENA_SZ  171720960ull

__device__ __align__(128) unsigned char g_arena[ARENA_SZ];
#define AP(T, off) ((T*)(g_arena + (off)))

// ---------------------------------------------------------------------------
// PTX helpers (base sm_103 target)
// ---------------------------------------------------------------------------
__device__ __forceinline__ uint32_t smem_u32(const void* p) {
    uint32_t a;
    asm("{ .reg .u64 t; cvta.to.shared.u64 t, %1; cvt.u32.u64 %0, t; }"
        : "=r"(a) : "l"(p));
    return a;
}
__device__ __forceinline__ void cpasync16(uint32_t s, const void* g) {
    asm volatile("cp.async.cg.shared.global [%0], [%1], 16;"
                 :: "r"(s), "l"(g) : "memory");
}
__device__ __forceinline__ void cp_commit() {
    asm volatile("cp.async.commit_group;" ::: "memory");
}
template <int N>
__device__ __forceinline__ void cp_wait() {
    asm volatile("cp.async.wait_group %0;" :: "n"(N) : "memory");
}
__device__ __forceinline__ void ldsm4(uint32_t* r, uint32_t a) {
    asm volatile("ldmatrix.sync.aligned.m8n8.x4.shared.b16 {%0,%1,%2,%3}, [%4];"
                 : "=r"(r[0]), "=r"(r[1]), "=r"(r[2]), "=r"(r[3]) : "r"(a));
}
__device__ __forceinline__ void mma16816(float* c, const uint32_t* a,
                                         const uint32_t* b) {
    asm volatile(
        "mma.sync.aligned.m16n8k16.row.col.f32.f16.f16.f32 "
        "{%0,%1,%2,%3}, {%4,%5,%6,%7}, {%8,%9}, {%0,%1,%2,%3};"
        : "+f"(c[0]), "+f"(c[1]), "+f"(c[2]), "+f"(c[3])
        : "r"(a[0]), "r"(a[1]), "r"(a[2]), "r"(a[3]), "r"(b[0]), "r"(b[1]));
}

// ---------------------------------------------------------------------------
// GEMM core (R5 config, proven): 128x128 CTA tile, kc=64, fp16 K-major.
// 256 threads, warp tile 64x32 (2x4 grid), 2 tiles/stage, 144B pitch,
// 3-stage ring, 1 sync/stage, 2 CTAs/SM. Separate head strides for A/B.
// ---------------------------------------------------------------------------
#define GP_PITCH  144
#define G_TILE    18432
#define G_STAGE   36864
#define G_SMEM    110592

__device__ __forceinline__ void ld_stage(
    uint32_t st, int tid, const __half* A, const __half* B, int lda, int ldb)
{
#pragma unroll
    for (int it = 0; it < 4; it++) {
        const int idx = it * 256 + tid;
        const int row = idx >> 3, seg = idx & 7;
        const uint32_t so = row * GP_PITCH + seg * 16;
        cpasync16(st + so,          (const char*)(A + (size_t)row * lda) + seg * 16);
        cpasync16(st + G_TILE + so, (const char*)(B + (size_t)row * ldb) + seg * 16);
    }
    cp_commit();
}

// S = total kc-stages; KPH = stages per head; hstA/hstB = per-head strides.
template <int S, int KPH>
__device__ __forceinline__ void gemm_mma(
    const __half* A0, const __half* B0, size_t hstA, size_t hstB,
    int lda, int ldb, uint32_t sb, float acc[4][4][4],
    int wm, int wn, int lane, int tid)
{
#pragma unroll
    for (int mt = 0; mt < 4; mt++)
#pragma unroll
        for (int nt = 0; nt < 4; nt++)
#pragma unroll
            for (int q = 0; q < 4; q++) acc[mt][nt][q] = 0.f;

    ld_stage(sb,           tid, A0,      B0,      lda, ldb);
    ld_stage(sb + G_STAGE, tid, A0 + 64, B0 + 64, lda, ldb);

    for (int s = 0; s < S; s++) {
        if (s < S - 1) cp_wait<1>(); else cp_wait<0>();
        __syncthreads();
        const int sn = s + 2;
        if (sn < S) {
            const int hh = sn / KPH, kt = (sn % KPH) * 64;
            ld_stage(sb + (sn % 3) * G_STAGE, tid,
                     A0 + hh * hstA + kt, B0 + hh * hstB + kt, lda, ldb);
        }
        const uint32_t bu = sb + (s % 3) * G_STAGE;
        const uint32_t Ab = bu, Bb = bu + G_TILE;
#pragma unroll
        for (int ks = 0; ks < 4; ks++) {
            uint32_t bq[4][2];
            const int bcol = ks * 16 + (((lane >> 3) & 1) << 3);
            const int brow_in = ((lane >> 4) << 3) + (lane & 7);
#pragma unroll
            for (int p = 0; p < 2; p++) {
                uint32_t r[4];
                const int brow = wn * 32 + p * 16 + brow_in;
                ldsm4(r, Bb + (uint32_t)brow * GP_PITCH + bcol * 2);
                bq[2 * p][0] = r[0]; bq[2 * p][1] = r[1];
                bq[2 * p + 1][0] = r[2]; bq[2 * p + 1][1] = r[3];
            }
            const int arow = wm * 64 + (lane & 15);
            const int acol = ks * 16 + (lane >> 4) * 8;
#pragma unroll
            for (int mt = 0; mt < 4; mt++) {
                uint32_t aq[4];
                ldsm4(aq, Ab + (uint32_t)(arow + mt * 16) * GP_PITCH + acol * 2);
#pragma unroll
                for (int nt = 0; nt < 4; nt++)
                    mma16816(acc[mt][nt], aq, bq[nt]);
            }
        }
    }
}

// ---------------------------------------------------------------------------
// G1 (per head h): y[hb][node][f] = sum_j attn[hb][node][j] * xT[b][f][j]
// ---------------------------------------------------------------------------
__global__ void __launch_bounds__(256, 2) g1_tc(int h) {
    extern __shared__ char dynsm[];
    const int tid = threadIdx.x;
    const int w = tid >> 5, lane = tid & 31;
    const int wm = w & 1, wn = w >> 1;
    const int b = blockIdx.z;
    const int z = h * NB + b;
    const int m0 = blockIdx.y * 128;   // node tile
    const int n0 = blockIdx.x * 128;   // f tile

    const __half* A0 = AP(__half, OFF_AH) + ((size_t)z * NN + m0) * NN;
    const __half* B0 = AP(__half, OFF_XT) + (size_t)b * NF * NN + (size_t)n0 * NN;

    float acc[4][4][4];
    gemm_mma<16, 16>(A0, B0, 0, 0, NN, NN, smem_u32(dynsm), acc, wm, wn, lane, tid);

    __half* y = AP(__half, OFF_Y) + (size_t)z * NN * NF;
#pragma unroll
    for (int mt = 0; mt < 4; mt++)
#pragma unroll
        for (int nt = 0; nt < 4; nt++)
#pragma unroll
            for (int hf = 0; hf < 2; hf++) {
                const int row = m0 + wm * 64 + mt * 16 + (lane >> 2) + hf * 8;
                const int col = n0 + wn * 32 + nt * 8 + (lane & 3) * 2;
                __half2 p;
                p.x = __float2half(acc[mt][nt][hf * 2 + 0]);
                p.y = __float2half(acc[mt][nt][hf * 2 + 1]);
                *(__half2*)(y + (size_t)row * NF + col) = p;
            }
}

// ---------------------------------------------------------------------------
// G2: out[b][node][fp] = (1/3) sum_h sum_f y[hb][node][f] * kT[h][fp][f] + bm
// ---------------------------------------------------------------------------
__global__ void __launch_bounds__(256, 2) g2_tc(float* __restrict__ out) {
    extern __shared__ char dynsm[];
    const int tid = threadIdx.x;
    const int w = tid >> 5, lane = tid & 31;
    const int wm = w & 1, wn = w >> 1;
    const int b = blockIdx.z;
    const int m0 = blockIdx.y * 128;   // node tile
    const int n0 = blockIdx.x * 128;   // fp tile

    const size_t hstA = (size_t)NB * NN * NF;   // head stride in y (hb = h*NB+b)
    const size_t hstB = (size_t)NFP * NF;       // head stride in kT
    const __half* A0 = AP(__half, OFF_Y)   + ((size_t)b * NN + m0) * NF;
    const __half* B0 = AP(__half, OFF_KTH) + (size_t)n0 * NF;

    float acc[4][4][4];
    gemm_mma<24, 8>(A0, B0, hstA, hstB, NF, NF, smem_u32(dynsm), acc, wm, wn, lane, tid);

    const float* bm = AP(float, OFF_BM);
    float* C = out + ((size_t)(NH * NB) + b) * NN * NN;
#pragma unroll
    for (int mt = 0; mt < 4; mt++)
#pragma unroll
        for (int nt = 0; nt < 4; nt++)
#pragma unroll
            for (int hf = 0; hf < 2; hf++) {
                const int row = m0 + wm * 64 + mt * 16 + (lane >> 2) + hf * 8;
                const int col = n0 + wn * 32 + nt * 8 + (lane & 3) * 2;
                float2 v;
                v.x = acc[mt][nt][hf * 2 + 0] * (1.f / 3.f) + bm[col + 0];
                v.y = acc[mt][nt][hf * 2 + 1] * (1.f / 3.f) + bm[col + 1];
                *(float2*)(C + (size_t)row * NN + col) = v;
            }
}

// ---------------------------------------------------------------------------
// Prep kernels
// ---------------------------------------------------------------------------
// x (b, n, f) fp32 -> xT (b, f, n) fp16
__global__ void prep_xT(const float* __restrict__ x) {
    __shared__ float t[32][33];
    const int b = blockIdx.z;
    const int n0 = blockIdx.x * 32, f0 = blockIdx.y * 32;
    const float* src = x + (size_t)b * NN * NF;
#pragma unroll
    for (int j = 0; j < 4; j++)
        t[threadIdx.y + j * 8][threadIdx.x] =
            src[(size_t)(n0 + threadIdx.y + j * 8) * NF + f0 + threadIdx.x];
    __syncthreads();
    __half* dst = AP(__half, OFF_XT) + (size_t)b * NF * NN;
#pragma unroll
    for (int j = 0; j < 4; j++) {
        float v = t[threadIdx.x][threadIdx.y + j * 8];
        dst[(size_t)(f0 + threadIdx.y + j * 8) * NN + n0 + threadIdx.x] =
            __float2half(v);
    }
}

// kernels (H, F, F_) -> kT (H, F_, F) fp16
__global__ void prep_kT(const float* __restrict__ kern) {
    __shared__ float t[32][33];
    const int h = blockIdx.z;
    const int fp0 = blockIdx.x * 32, f0 = blockIdx.y * 32;
    const float* src = kern + (size_t)h * NF * NFP;
#pragma unroll
    for (int j = 0; j < 4; j++)
        t[threadIdx.y + j * 8][threadIdx.x] =
            src[(size_t)(f0 + threadIdx.y + j * 8) * NFP + fp0 + threadIdx.x];
    __syncthreads();
    __half* dst = AP(__half, OFF_KTH) + (size_t)h * NFP * NF;
#pragma unroll
    for (int j = 0; j < 4; j++) {
        float v = t[threadIdx.x][threadIdx.y + j * 8];
        dst[(size_t)(fp0 + threadIdx.y + j * 8) * NF + f0 + threadIdx.x] =
            __float2half(v);
    }
}

// w2[h][f] = sum_fp kernels[h][f][fp] * a[h][fp]   (single head)
__global__ void w2k_h(const float* __restrict__ kern,
                      const float* __restrict__ as, const float* __restrict__ an,
                      int h) {
    const int f = blockIdx.x * 8 + (threadIdx.x >> 5);   // 0..511
    const int lane = threadIdx.x & 31;
    const float* row = kern + ((size_t)h * NF + f) * NFP;
    const float* a1 = as + (size_t)h * NFP;
    const float* a2 = an + (size_t)h * NFP;
    float s1 = 0.f, s2 = 0.f;
#pragma unroll
    for (int it = 0; it < 8; it++) {
        int k = it * 128 + lane * 4;
        float4 kv = *(const float4*)(row + k);
        float4 v1 = *(const float4*)(a1 + k);
        float4 v2 = *(const float4*)(a2 + k);
        s1 += kv.x * v1.x + kv.y * v1.y + kv.z * v1.z + kv.w * v1.w;
        s2 += kv.x * v2.x + kv.y * v2.y + kv.z * v2.z + kv.w * v2.w;
    }
#pragma unroll
    for (int o = 16; o > 0; o >>= 1) {
        s1 += __shfl_xor_sync(0xFFFFFFFFu, s1, o);
        s2 += __shfl_xor_sync(0xFFFFFFFFu, s2, o);
    }
    if (lane == 0) {
        AP(float, OFF_W2S)[(size_t)h * NF + f] = s1;
        AP(float, OFF_W2N)[(size_t)h * NF + f] = s2;
    }
}

// s_self[h,b,n] = x[b,n,:] . w2s[h]; s_neigh likewise (single head)
__global__ void __launch_bounds__(256) s_comp_h(const float* __restrict__ x, int h) {
    __shared__ float ws[NF], wn_[NF];
    for (int i = threadIdx.x; i < NF; i += 256) {
        ws[i]  = AP(float, OFF_W2S)[(size_t)h * NF + i];
        wn_[i] = AP(float, OFF_W2N)[(size_t)h * NF + i];
    }
    __syncthreads();
    const int gw = blockIdx.x * 8 + (threadIdx.x >> 5);   // 0..16383
    const int lane = threadIdx.x & 31;
    const int b = gw >> 10, n = gw & 1023;
    const float* xr = x + ((size_t)b * NN + n) * NF;
    float a = 0.f, c = 0.f;
#pragma unroll
    for (int it = 0; it < 4; it++) {
        int f = it * 128 + lane * 4;
        float4 xv = *(const float4*)(xr + f);
        float4 w = *(const float4*)&ws[f];
        float4 u = *(const float4*)&wn_[f];
        a += xv.x * w.x + xv.y * w.y + xv.z * w.z + xv.w * w.w;
        c += xv.x * u.x + xv.y * u.y + xv.z * u.z + xv.w * u.w;
    }
#pragma unroll
    for (int o = 16; o > 0; o >>= 1) {
        a += __shfl_xor_sync(0xFFFFFFFFu, a, o);
        c += __shfl_xor_sync(0xFFFFFFFFu, c, o);
    }
    if (lane == 0) {
        AP(float, OFF_SS)[((size_t)h * NB + b) * NN + n] = a;
        AP(float, OFF_SN)[((size_t)h * NB + b) * NN + n] = c;
    }
}

// Per-(h,b): M = max_j c_j; E1 = e^{c-M}; E2 = e^{0.2(c-M)}
__global__ void __launch_bounds__(1024) prep_e(int h) {
    __shared__ float red[32];
    const int hb = h * NB + blockIdx.x;
    const int tid = threadIdx.x;
    const float cv = AP(float, OFF_SN)[(size_t)hb * NN + tid];
    float m = cv;
#pragma unroll
    for (int o = 16; o > 0; o >>= 1) m = fmaxf(m, __shfl_xor_sync(0xFFFFFFFFu, m, o));
    if ((tid & 31) == 0) red[tid >> 5] = m;
    __syncthreads();
    if (tid < 32) {
        float t = red[tid];
#pragma unroll
        for (int o = 16; o > 0; o >>= 1) t = fmaxf(t, __shfl_xor_sync(0xFFFFFFFFu, t, o));
        if (tid == 0) red[0] = t;
    }
    __syncthreads();
    const float M = red[0];
    AP(float, OFF_E1)[(size_t)hb * NN + tid] = __expf(cv - M);
    AP(float, OFF_E2)[(size_t)hb * NN + tid] = __expf(0.2f * (cv - M));
    if (tid == 0) AP(float, OFF_M)[hb] = M;
}

// Exp-free per-head softmax; writes fp16 attn only.
// attn[i][j] = (t>=0 ? a*E1[j] : b*E2[j]) / rowsum, t = s_i + c_j.
__global__ void __launch_bounds__(256) sm16(int h) {
    __shared__ float c[NN], e1[NN], e2[NN];
    const int w    = threadIdx.x >> 5;
    const int lane = threadIdx.x & 31;
    const int rloc = blockIdx.x * 8;                  // row within head
    const int hb = h * NB + (rloc >> 10);
    const float* cn = AP(float, OFF_SN) + (size_t)hb * NN;
    const float* p1 = AP(float, OFF_E1) + (size_t)hb * NN;
    const float* p2 = AP(float, OFF_E2) + (size_t)hb * NN;
    for (int i = threadIdx.x; i < NN; i += 256) {
        c[i]  = cn[i];
        e1[i] = p1[i];
        e2[i] = p2[i];
    }
    __syncthreads();

    const size_t r = (size_t)hb * NN + (rloc & 1023) + w;
    const float s = AP(float, OFF_SS)[r];
    const float M = AP(float, OFF_M)[hb];
    const float sm = s + M;
    const float m = (sm >= 0.f) ? sm : 0.2f * sm;     // row max of leaky
    const float al = __expf(sm - m);
    const float be = __expf(0.2f * sm - m);

    float ev[32];
    float sum = 0.f;
#pragma unroll
    for (int it = 0; it < 32; it++) {
        const int j = it * 32 + lane;
        const float t = s + c[j];
        const float v = (t >= 0.f) ? e1[j] * al : e2[j] * be;
        ev[it] = v;
        sum += v;
    }
#pragma unroll
    for (int o = 16; o > 0; o >>= 1) sum += __shfl_xor_sync(0xFFFFFFFFu, sum, o);
    const float inv = 1.f / sum;

    __half* ah = AP(__half, OFF_AH) + r * NN;
#pragma unroll
    for (int it = 0; it < 32; it++)
        ah[it * 32 + lane] = __float2half(ev[it] * inv);
}

// fp16 attn -> fp32 d_out slices (bandwidth-only; overlaps the GEMMs)
__global__ void attn32(float* __restrict__ out, int h) {
    const size_t i = (size_t)blockIdx.x * 256 + threadIdx.x;   // x4 elements
    const __half2* src = (const __half2*)(AP(__half, OFF_AH) + (size_t)h * NB * NN * NN);
    float* dst = out + (size_t)h * NB * NN * NN;
    __half2 a = src[2 * i], b = src[2 * i + 1];
    float2 fa = __half22float2(a), fb = __half22float2(b);
    float4 v; v.x = fa.x; v.y = fa.y; v.z = fb.x; v.w = fb.y;
    ((float4*)dst)[i] = v;
}

__global__ void bias_mean(const float* __restrict__ biases) {
    int k = blockIdx.x * 256 + threadIdx.x;
    AP(float, OFF_BM)[k] =
        (biases[k] + biases[NFP + k] + biases[2 * NFP + k]) * (1.f / 3.f);
}

// ---------------------------------------------------------------------------
// Launch DAG (all side-stream tails joined back to stream 0 before capture end):
//   s1: per-head chains h0,h1,h2 (w2k_h -> s_comp_h -> prep_e -> sm16 [esm_h]),
//       then attn32 x3 [es1end].
//   0 : prep_xT, prep_kT, bias_mean [eprep]; (wait esm0) g1(0)
//   s2: (wait eprep,esm1) g1(1) [eg1b];  s3: (wait eprep,esm2) g1(2) [eg1c]
//   0 : (wait eg1b,eg1c,es1end) g2
// ---------------------------------------------------------------------------
extern "C" void kernel_launch(void* const* d_in, const int* in_sizes, int n_in,
                              void* d_out, int out_size)
{
    const float* x      = (const float*)d_in[0];
    const float* kern   = (const float*)d_in[1];
    const float* biases = (const float*)d_in[2];
    const float* aself  = (const float*)d_in[3];
    const float* aneigh = (const float*)d_in[4];
    float* out = (float*)d_out;

    static cudaStream_t s1 = nullptr, s2 = nullptr, s3 = nullptr;
    static cudaEvent_t efork = nullptr, eprep = nullptr, es1end = nullptr;
    static cudaEvent_t esm[3] = {nullptr, nullptr, nullptr};
    static cudaEvent_t eg1b = nullptr, eg1c = nullptr;
    static bool attr_done = false;
    if (s1 == nullptr) {
        cudaStreamCreateWithFlags(&s1, cudaStreamNonBlocking);
        cudaStreamCreateWithFlags(&s2, cudaStreamNonBlocking);
        cudaStreamCreateWithFlags(&s3, cudaStreamNonBlocking);
        cudaEventCreateWithFlags(&efork, cudaEventDisableTiming);
        cudaEventCreateWithFlags(&eprep, cudaEventDisableTiming);
        cudaEventCreateWithFlags(&es1end, cudaEventDisableTiming);
        for (int h = 0; h < 3; h++)
            cudaEventCreateWithFlags(&esm[h], cudaEventDisableTiming);
        cudaEventCreateWithFlags(&eg1b, cudaEventDisableTiming);
        cudaEventCreateWithFlags(&eg1c, cudaEventDisableTiming);
    }
    if (!attr_done) {
        cudaFuncSetAttribute(g1_tc, cudaFuncAttributeMaxDynamicSharedMemorySize, G_SMEM);
        cudaFuncSetAttribute(g2_tc, cudaFuncAttributeMaxDynamicSharedMemorySize, G_SMEM);
        attr_done = true;
    }

    // Fork
    cudaEventRecord(efork, 0);
    cudaStreamWaitEvent(s1, efork, 0);

    // Side stream: per-head attn chains (h0 first = shortest critical path)
    for (int h = 0; h < 3; h++) {
        w2k_h<<<NF / 8, 256, 0, s1>>>(kern, aself, aneigh, h);
        s_comp_h<<<(NB * NN) / 8, 256, 0, s1>>>(x, h);
        prep_e<<<NB, 1024, 0, s1>>>(h);
        sm16<<<(NB * NN) / 8, 256, 0, s1>>>(h);
        cudaEventRecord(esm[h], s1);
    }
    for (int h = 0; h < 3; h++)
        attn32<<<(NB * NN * NN / 4) / 256, 256, 0, s1>>>(out, h);
    cudaEventRecord(es1end, s1);

    // Main stream: operand prep
    prep_xT<<<dim3(NN / 32, NF / 32, NB), dim3(32, 8)>>>(x);
    prep_kT<<<dim3(NFP / 32, NF / 32, NH), dim3(32, 8)>>>(kern);
    bias_mean<<<NFP / 256, 256>>>(biases);
    cudaEventRecord(eprep, 0);

    // g1 per head: h0 on main, h1/h2 on s2/s3
    cudaStreamWaitEvent(0, esm[0], 0);
    g1_tc<<<dim3(NF / 128, NN / 128, NB), 256, G_SMEM>>>(0);

    cudaStreamWaitEvent(s2, eprep, 0);
    cudaStreamWaitEvent(s2, esm[1], 0);
    g1_tc<<<dim3(NF / 128, NN / 128, NB), 256, G_SMEM, s2>>>(1);
    cudaEventRecord(eg1b, s2);

    cudaStreamWaitEvent(s3, eprep, 0);
    cudaStreamWaitEvent(s3, esm[2], 0);
    g1_tc<<<dim3(NF / 128, NN / 128, NB), 256, G_SMEM, s3>>>(2);
    cudaEventRecord(eg1c, s3);

    // g2 after all of g1 and the side-stream tail (joins s1 for capture)
    cudaStreamWaitEvent(0, eg1b, 0);
    cudaStreamWaitEvent(0, eg1c, 0);
    cudaStreamWaitEvent(0, es1end, 0);
    g2_tc<<<dim3(NFP / 128, NN / 128, NB), 256, G_SMEM>>>(out);
}

// round 14
// speedup vs baseline: 1.2020x; 1.2020x over previous
#include <cuda_runtime.h>
#include <cuda_fp16.h>
#include <stdint.h>

#define NH 3
#define NB 16
#define NN 1024
#define NF 512
#define NFP 1024

// ---------------------------------------------------------------------------
// Scratch arena
// ---------------------------------------------------------------------------
#define OFF_XH    0ull            // x fp16 [b][n][f]          16 MB
#define OFF_KTH   16777216ull     // kernels^T fp16 [h][fp][f]  3 MB
#define OFF_Y     19922944ull     // y fp16 [hb][n][f]         48 MB
#define OFF_S1    70254592ull     // suffix sums fp32 [hb][idx][f]  96 MB
#define OFF_S2    170917888ull    // prefix sums fp32 [hb][idx][f]  96 MB
#define OFF_CP1   271581184ull    // chunk partials/offsets fp32 [hb][16][f]
#define OFF_CP2   273154048ull
#define OFF_CS    274726912ull    // sorted c
#define OFF_PERM  274923520ull
#define OFF_W1    275120128ull    // e^{c-M}
#define OFF_W2    275316736ull    // e^{0.2(c-M)}
#define OFF_Z1S   275513344ull
#define OFF_Z2P   275709952ull
#define OFF_MM    275906560ull    // per-hb max c
#define OFF_W2S   275906816ull
#define OFF_W2N   275912960ull
#define OFF_SS    275919104ull
#define OFF_SN    276115712ull
#define OFF_BM    276312320ull
#define ARENA_SZ  276316416ull

__device__ __align__(128) unsigned char g_arena[ARENA_SZ];
#define AP(T, off) ((T*)(g_arena + (off)))

// ---------------------------------------------------------------------------
// PTX helpers (base sm_103 target)
// ---------------------------------------------------------------------------
__device__ __forceinline__ uint32_t smem_u32(const void* p) {
    uint32_t a;
    asm("{ .reg .u64 t; cvta.to.shared.u64 t, %1; cvt.u32.u64 %0, t; }"
        : "=r"(a) : "l"(p));
    return a;
}
__device__ __forceinline__ void cpasync16(uint32_t s, const void* g) {
    asm volatile("cp.async.cg.shared.global [%0], [%1], 16;"
                 :: "r"(s), "l"(g) : "memory");
}
__device__ __forceinline__ void cp_commit() {
    asm volatile("cp.async.commit_group;" ::: "memory");
}
template <int N>
__device__ __forceinline__ void cp_wait() {
    asm volatile("cp.async.wait_group %0;" :: "n"(N) : "memory");
}
__device__ __forceinline__ void ldsm4(uint32_t* r, uint32_t a) {
    asm volatile("ldmatrix.sync.aligned.m8n8.x4.shared.b16 {%0,%1,%2,%3}, [%4];"
                 : "=r"(r[0]), "=r"(r[1]), "=r"(r[2]), "=r"(r[3]) : "r"(a));
}
__device__ __forceinline__ void mma16816(float* c, const uint32_t* a,
                                         const uint32_t* b) {
    asm volatile(
        "mma.sync.aligned.m16n8k16.row.col.f32.f16.f16.f32 "
        "{%0,%1,%2,%3}, {%4,%5,%6,%7}, {%8,%9}, {%0,%1,%2,%3};"
        : "+f"(c[0]), "+f"(c[1]), "+f"(c[2]), "+f"(c[3])
        : "r"(a[0]), "r"(a[1]), "r"(a[2]), "r"(a[3]), "r"(b[0]), "r"(b[1]));
}

// ---------------------------------------------------------------------------
// GEMM core (R5 config, proven): 128x128 CTA tile, kc=64, fp16 K-major.
// ---------------------------------------------------------------------------
#define GP_PITCH  144
#define G_TILE    18432
#define G_STAGE   36864
#define G_SMEM    110592

__device__ __forceinline__ void ld_stage(
    uint32_t st, int tid, const __half* A, const __half* B, int lda, int ldb)
{
#pragma unroll
    for (int it = 0; it < 4; it++) {
        const int idx = it * 256 + tid;
        const int row = idx >> 3, seg = idx & 7;
        const uint32_t so = row * GP_PITCH + seg * 16;
        cpasync16(st + so,          (const char*)(A + (size_t)row * lda) + seg * 16);
        cpasync16(st + G_TILE + so, (const char*)(B + (size_t)row * ldb) + seg * 16);
    }
    cp_commit();
}

template <int S, int KPH>
__device__ __forceinline__ void gemm_mma(
    const __half* A0, const __half* B0, size_t hstA, size_t hstB,
    int lda, int ldb, uint32_t sb, float acc[4][4][4],
    int wm, int wn, int lane, int tid)
{
#pragma unroll
    for (int mt = 0; mt < 4; mt++)
#pragma unroll
        for (int nt = 0; nt < 4; nt++)
#pragma unroll
            for (int q = 0; q < 4; q++) acc[mt][nt][q] = 0.f;

    ld_stage(sb,           tid, A0,      B0,      lda, ldb);
    ld_stage(sb + G_STAGE, tid, A0 + 64, B0 + 64, lda, ldb);

    for (int s = 0; s < S; s++) {
        if (s < S - 1) cp_wait<1>(); else cp_wait<0>();
        __syncthreads();
        const int sn = s + 2;
        if (sn < S) {
            const int hh = sn / KPH, kt = (sn % KPH) * 64;
            ld_stage(sb + (sn % 3) * G_STAGE, tid,
                     A0 + hh * hstA + kt, B0 + hh * hstB + kt, lda, ldb);
        }
        const uint32_t bu = sb + (s % 3) * G_STAGE;
        const uint32_t Ab = bu, Bb = bu + G_TILE;
#pragma unroll
        for (int ks = 0; ks < 4; ks++) {
            uint32_t bq[4][2];
            const int bcol = ks * 16 + (((lane >> 3) & 1) << 3);
            const int brow_in = ((lane >> 4) << 3) + (lane & 7);
#pragma unroll
            for (int p = 0; p < 2; p++) {
                uint32_t r[4];
                const int brow = wn * 32 + p * 16 + brow_in;
                ldsm4(r, Bb + (uint32_t)brow * GP_PITCH + bcol * 2);
                bq[2 * p][0] = r[0]; bq[2 * p][1] = r[1];
                bq[2 * p + 1][0] = r[2]; bq[2 * p + 1][1] = r[3];
            }
            const int arow = wm * 64 + (lane & 15);
            const int acol = ks * 16 + (lane >> 4) * 8;
#pragma unroll
            for (int mt = 0; mt < 4; mt++) {
                uint32_t aq[4];
                ldsm4(aq, Ab + (uint32_t)(arow + mt * 16) * GP_PITCH + acol * 2);
#pragma unroll
                for (int nt = 0; nt < 4; nt++)
                    mma16816(acc[mt][nt], aq, bq[nt]);
            }
        }
    }
}

// ---------------------------------------------------------------------------
// G2: out[b][node][fp] = (1/3) sum_h sum_f y[hb][node][f] * kT[h][fp][f] + bm
// ---------------------------------------------------------------------------
__global__ void __launch_bounds__(256, 2) g2_tc(float* __restrict__ out) {
    extern __shared__ char dynsm[];
    const int tid = threadIdx.x;
    const int w = tid >> 5, lane = tid & 31;
    const int wm = w & 1, wn = w >> 1;
    const int b = blockIdx.z;
    const int m0 = blockIdx.y * 128;   // node tile
    const int n0 = blockIdx.x * 128;   // fp tile

    const size_t hstA = (size_t)NB * NN * NF;
    const size_t hstB = (size_t)NFP * NF;
    const __half* A0 = AP(__half, OFF_Y)   + ((size_t)b * NN + m0) * NF;
    const __half* B0 = AP(__half, OFF_KTH) + (size_t)n0 * NF;

    float acc[4][4][4];
    gemm_mma<24, 8>(A0, B0, hstA, hstB, NF, NF, smem_u32(dynsm), acc, wm, wn, lane, tid);

    const float* bm = AP(float, OFF_BM);
    float* C = out + ((size_t)(NH * NB) + b) * NN * NN;
#pragma unroll
    for (int mt = 0; mt < 4; mt++)
#pragma unroll
        for (int nt = 0; nt < 4; nt++)
#pragma unroll
            for (int hf = 0; hf < 2; hf++) {
                const int row = m0 + wm * 64 + mt * 16 + (lane >> 2) + hf * 8;
                const int col = n0 + wn * 32 + nt * 8 + (lane & 3) * 2;
                float2 v;
                v.x = acc[mt][nt][hf * 2 + 0] * (1.f / 3.f) + bm[col + 0];
                v.y = acc[mt][nt][hf * 2 + 1] * (1.f / 3.f) + bm[col + 1];
                *(float2*)(C + (size_t)row * NN + col) = v;
            }
}

// ---------------------------------------------------------------------------
// Prep + logits chain
// ---------------------------------------------------------------------------
__global__ void prep_x(const float* __restrict__ x) {
    const size_t i = (size_t)blockIdx.x * 256 + threadIdx.x;
    float4 v = ((const float4*)x)[i];
    union { __half h[4]; uint2 u; } o;
    o.h[0] = __float2half(v.x); o.h[1] = __float2half(v.y);
    o.h[2] = __float2half(v.z); o.h[3] = __float2half(v.w);
    ((uint2*)AP(unsigned char, OFF_XH))[i] = o.u;
}

__global__ void prep_kT(const float* __restrict__ kern) {
    __shared__ float t[32][33];
    const int h = blockIdx.z;
    const int fp0 = blockIdx.x * 32, f0 = blockIdx.y * 32;
    const float* src = kern + (size_t)h * NF * NFP;
#pragma unroll
    for (int j = 0; j < 4; j++)
        t[threadIdx.y + j * 8][threadIdx.x] =
            src[(size_t)(f0 + threadIdx.y + j * 8) * NFP + fp0 + threadIdx.x];
    __syncthreads();
    __half* dst = AP(__half, OFF_KTH) + (size_t)h * NFP * NF;
#pragma unroll
    for (int j = 0; j < 4; j++) {
        float v = t[threadIdx.x][threadIdx.y + j * 8];
        dst[(size_t)(fp0 + threadIdx.y + j * 8) * NF + f0 + threadIdx.x] =
            __float2half(v);
    }
}

__global__ void w2k(const float* __restrict__ kern,
                    const float* __restrict__ as, const float* __restrict__ an) {
    const int gw = blockIdx.x * 8 + (threadIdx.x >> 5);
    const int lane = threadIdx.x & 31;
    const int h = gw >> 9, f = gw & 511;
    const float* row = kern + ((size_t)h * NF + f) * NFP;
    const float* a1 = as + (size_t)h * NFP;
    const float* a2 = an + (size_t)h * NFP;
    float s1 = 0.f, s2 = 0.f;
#pragma unroll
    for (int it = 0; it < 8; it++) {
        int k = it * 128 + lane * 4;
        float4 kv = *(const float4*)(row + k);
        float4 v1 = *(const float4*)(a1 + k);
        float4 v2 = *(const float4*)(a2 + k);
        s1 += kv.x * v1.x + kv.y * v1.y + kv.z * v1.z + kv.w * v1.w;
        s2 += kv.x * v2.x + kv.y * v2.y + kv.z * v2.z + kv.w * v2.w;
    }
#pragma unroll
    for (int o = 16; o > 0; o >>= 1) {
        s1 += __shfl_xor_sync(0xFFFFFFFFu, s1, o);
        s2 += __shfl_xor_sync(0xFFFFFFFFu, s2, o);
    }
    if (lane == 0) {
        AP(float, OFF_W2S)[(size_t)h * NF + f] = s1;
        AP(float, OFF_W2N)[(size_t)h * NF + f] = s2;
    }
}

__global__ void __launch_bounds__(256) s_comp(const float* __restrict__ x) {
    __shared__ float ws[NH * NF], wn_[NH * NF];
    for (int i = threadIdx.x; i < NH * NF; i += 256) {
        ws[i]  = AP(float, OFF_W2S)[i];
        wn_[i] = AP(float, OFF_W2N)[i];
    }
    __syncthreads();
    const int gw = blockIdx.x * 8 + (threadIdx.x >> 5);
    const int lane = threadIdx.x & 31;
    const int b = gw >> 10, n = gw & 1023;
    const float* xr = x + ((size_t)b * NN + n) * NF;
    float a[3] = {0.f, 0.f, 0.f}, c[3] = {0.f, 0.f, 0.f};
#pragma unroll
    for (int it = 0; it < 4; it++) {
        int f = it * 128 + lane * 4;
        float4 xv = *(const float4*)(xr + f);
#pragma unroll
        for (int h = 0; h < 3; h++) {
            float4 w = *(const float4*)&ws[h * NF + f];
            float4 u = *(const float4*)&wn_[h * NF + f];
            a[h] += xv.x * w.x + xv.y * w.y + xv.z * w.z + xv.w * w.w;
            c[h] += xv.x * u.x + xv.y * u.y + xv.z * u.z + xv.w * u.w;
        }
    }
#pragma unroll
    for (int h = 0; h < 3; h++) {
#pragma unroll
        for (int o = 16; o > 0; o >>= 1) {
            a[h] += __shfl_xor_sync(0xFFFFFFFFu, a[h], o);
            c[h] += __shfl_xor_sync(0xFFFFFFFFu, c[h], o);
        }
    }
    if (lane == 0) {
#pragma unroll
        for (int h = 0; h < 3; h++) {
            AP(float, OFF_SS)[(size_t)h * NB * NN + b * NN + n] = a[h];
            AP(float, OFF_SN)[(size_t)h * NB * NN + b * NN + n] = c[h];
        }
    }
}

// Exact fp32 row softmax -> d_out attn slices only (side stream).
__global__ void __launch_bounds__(256) attn_softmax(float* __restrict__ out) {
    __shared__ float c[NN];
    const int w    = threadIdx.x >> 5;
    const int lane = threadIdx.x & 31;
    const size_t r0 = (size_t)blockIdx.x * 8;
    const size_t hb = r0 >> 10;
    const float* cn = AP(float, OFF_SN) + hb * NN;
    for (int i = threadIdx.x; i < NN; i += 256) c[i] = cn[i];
    __syncthreads();

    const size_t r = r0 + w;
    const float a = AP(float, OFF_SS)[r];

    float ev[32];
    float m = -1e30f;
#pragma unroll
    for (int it = 0; it < 32; it++) {
        float t = a + c[it * 32 + lane];
        t = (t >= 0.f) ? t : 0.2f * t;
        ev[it] = t;
        m = fmaxf(m, t);
    }
#pragma unroll
    for (int o = 16; o > 0; o >>= 1) m = fmaxf(m, __shfl_xor_sync(0xFFFFFFFFu, m, o));
    float s = 0.f;
#pragma unroll
    for (int it = 0; it < 32; it++) {
        float e = __expf(ev[it] - m);
        ev[it] = e;
        s += e;
    }
#pragma unroll
    for (int o = 16; o > 0; o >>= 1) s += __shfl_xor_sync(0xFFFFFFFFu, s, o);
    const float inv = 1.f / s;

    float* orow = out + r * NN;
#pragma unroll
    for (int it = 0; it < 32; it++)
        orow[it * 32 + lane] = ev[it] * inv;
}

__global__ void bias_mean(const float* __restrict__ biases) {
    int k = blockIdx.x * 256 + threadIdx.x;
    AP(float, OFF_BM)[k] =
        (biases[k] + biases[NFP + k] + biases[2 * NFP + k]) * (1.f / 3.f);
}

// ---------------------------------------------------------------------------
// sort_c (R8-verified): bitonic sort of c per hb; emits perm, cs, w1, w2,
// scalar suffix/prefix sums z1s/z2p, and M.
// ---------------------------------------------------------------------------
__global__ void __launch_bounds__(1024) sort_c() {
    __shared__ float key[1024];
    __shared__ int   val[1024];
    __shared__ float buf[1024];
    const int hb = blockIdx.x, tid = threadIdx.x;
    key[tid] = AP(float, OFF_SN)[(size_t)hb * NN + tid];
    val[tid] = tid;
    __syncthreads();
    for (int ksz = 2; ksz <= 1024; ksz <<= 1)
        for (int j = ksz >> 1; j > 0; j >>= 1) {
            const int ixj = tid ^ j;
            if (ixj > tid) {
                const bool asc = ((tid & ksz) == 0);
                float a = key[tid], bb = key[ixj];
                if ((a > bb) == asc) {
                    key[tid] = bb; key[ixj] = a;
                    int tv = val[tid]; val[tid] = val[ixj]; val[ixj] = tv;
                }
            }
            __syncthreads();
        }
    const float M1 = key[1023];
    const float cv = key[tid];
    const float w1 = __expf(cv - M1);
    const float w2 = __expf(0.2f * (cv - M1));
    AP(float, OFF_CS)[(size_t)hb * NN + tid] = cv;
    AP(int,   OFF_PERM)[(size_t)hb * NN + tid] = val[tid];
    AP(float, OFF_W1)[(size_t)hb * NN + tid] = w1;
    AP(float, OFF_W2)[(size_t)hb * NN + tid] = w2;
    if (tid == 0) AP(float, OFF_MM)[hb] = M1;
    __syncthreads();

    buf[tid] = w2;                       // z2pre inclusive forward
    __syncthreads();
    for (int off = 1; off < 1024; off <<= 1) {
        float v = (tid >= off) ? buf[tid - off] : 0.f;
        __syncthreads();
        buf[tid] += v;
        __syncthreads();
    }
    AP(float, OFF_Z2P)[(size_t)hb * NN + tid] = buf[tid];
    __syncthreads();

    buf[1023 - tid] = w1;                // z1suf inclusive (reversed)
    __syncthreads();
    for (int off = 1; off < 1024; off <<= 1) {
        float v = (tid >= off) ? buf[tid - off] : 0.f;
        __syncthreads();
        buf[tid] += v;
        __syncthreads();
    }
    AP(float, OFF_Z1S)[(size_t)hb * NN + (1023 - tid)] = buf[tid];
}

// ---------------------------------------------------------------------------
// Hierarchical weighted scans of x rows in sorted order (per hb, 16 chunks of 64)
// ---------------------------------------------------------------------------
// Phase A: chunk totals T1/T2 per f.
__global__ void __launch_bounds__(256) scan_part() {
    __shared__ int   sp[64];
    __shared__ float sw1[64], sw2[64];
    const int hb = blockIdx.x, ch = blockIdx.y;
    const int b = hb & 15;
    const int t = threadIdx.x;            // f pair = 2t
    if (t < 64) {
        sp[t]  = AP(int,   OFF_PERM)[(size_t)hb * NN + ch * 64 + t];
        sw1[t] = AP(float, OFF_W1)[(size_t)hb * NN + ch * 64 + t];
        sw2[t] = AP(float, OFF_W2)[(size_t)hb * NN + ch * 64 + t];
    }
    __syncthreads();
    const __half* xb = AP(__half, OFF_XH) + (size_t)b * NN * NF;
    float2 a1 = make_float2(0.f, 0.f), a2 = make_float2(0.f, 0.f);
#pragma unroll 4
    for (int i = 0; i < 64; i++) {
        __half2 h = *(const __half2*)(xb + (size_t)sp[i] * NF + 2 * t);
        float2 f = __half22float2(h);
        a1.x += sw1[i] * f.x; a1.y += sw1[i] * f.y;
        a2.x += sw2[i] * f.x; a2.y += sw2[i] * f.y;
    }
    *(float2*)(AP(float, OFF_CP1) + ((size_t)hb * 16 + ch) * NF + 2 * t) = a1;
    *(float2*)(AP(float, OFF_CP2) + ((size_t)hb * 16 + ch) * NF + 2 * t) = a2;
}

// Phase B: in-place exclusive offsets (suffix for S1, prefix for S2).
__global__ void __launch_bounds__(512) scan_off() {
    const int hb = blockIdx.x;
    const int f = threadIdx.x;
    float* cp1 = AP(float, OFF_CP1) + (size_t)hb * 16 * NF + f;
    float* cp2 = AP(float, OFF_CP2) + (size_t)hb * 16 * NF + f;
    float run = 0.f;
    for (int c = 15; c >= 0; c--) {
        float v = cp1[(size_t)c * NF];
        cp1[(size_t)c * NF] = run;
        run += v;
    }
    run = 0.f;
    for (int c = 0; c < 16; c++) {
        float v = cp2[(size_t)c * NF];
        cp2[(size_t)c * NF] = run;
        run += v;
    }
}

// Phase C: full S1 (suffix, fp32) and S2 (prefix, fp32); chunk rows in smem.
#define SW_DSM 65536
__global__ void __launch_bounds__(256) scan_write() {
    extern __shared__ __half rows[];     // [64][512]
    __shared__ int   sp[64];
    __shared__ float sw1[64], sw2[64];
    const int hb = blockIdx.x, ch = blockIdx.y;
    const int b = hb & 15;
    const int t = threadIdx.x;            // f pair = 2t
    if (t < 64) {
        sp[t]  = AP(int,   OFF_PERM)[(size_t)hb * NN + ch * 64 + t];
        sw1[t] = AP(float, OFF_W1)[(size_t)hb * NN + ch * 64 + t];
        sw2[t] = AP(float, OFF_W2)[(size_t)hb * NN + ch * 64 + t];
    }
    __syncthreads();
    const __half* xb = AP(__half, OFF_XH) + (size_t)b * NN * NF;
#pragma unroll 4
    for (int i = 0; i < 64; i++)
        *(__half2*)(rows + i * NF + 2 * t) =
            *(const __half2*)(xb + (size_t)sp[i] * NF + 2 * t);
    __syncthreads();

    const size_t base = (size_t)hb * NN + ch * 64;
    float2 r1 = *(float2*)(AP(float, OFF_CP1) + ((size_t)hb * 16 + ch) * NF + 2 * t);
    for (int i = 63; i >= 0; i--) {
        float2 f = __half22float2(*(__half2*)(rows + i * NF + 2 * t));
        r1.x += sw1[i] * f.x; r1.y += sw1[i] * f.y;
        *(float2*)(AP(float, OFF_S1) + (base + i) * NF + 2 * t) = r1;
    }
    float2 r2 = *(float2*)(AP(float, OFF_CP2) + ((size_t)hb * 16 + ch) * NF + 2 * t);
    for (int i = 0; i < 64; i++) {
        float2 f = __half22float2(*(__half2*)(rows + i * NF + 2 * t));
        r2.x += sw2[i] * f.x; r2.y += sw2[i] * f.y;
        *(float2*)(AP(float, OFF_S2) + (base + i) * NF + 2 * t) = r2;
    }
}

// y[hb][row][:] = (S1[k] + q*S2[k-1]) / (z1s[k] + q*z2p[k-1]); fp16 out.
__global__ void __launch_bounds__(256) combine_y() {
    __shared__ float cs[NN];
    __shared__ int   sk[8];
    __shared__ float sq[8], siz[8];
    const int hb = blockIdx.y;
    const int r0 = blockIdx.x * 8;
    const int w = threadIdx.x >> 5, lane = threadIdx.x & 31;
    const float* csg = AP(float, OFF_CS) + (size_t)hb * NN;
    for (int i = threadIdx.x; i < NN; i += 256) cs[i] = csg[i];
    __syncthreads();

    const int row = r0 + w;
    const float s = AP(float, OFF_SS)[(size_t)hb * NN + row];
    if (lane == 0) {
        int lo = 0, hi = NN;
        while (lo < hi) {
            int mid = (lo + hi) >> 1;
            if (s + cs[mid] >= 0.f) hi = mid; else lo = mid + 1;
        }
        const float q = __expf(-0.8f * (s + AP(float, OFF_MM)[hb]));
        const float z1 = (lo < NN) ? AP(float, OFF_Z1S)[(size_t)hb * NN + lo] : 0.f;
        const float z2 = (lo > 0) ? AP(float, OFF_Z2P)[(size_t)hb * NN + lo - 1] : 0.f;
        sk[w] = lo; sq[w] = q; siz[w] = 1.f / (z1 + q * z2);
    }
    __syncwarp();
    const int k = sk[w];
    const float q = sq[w], iz = siz[w];
    const int k1 = (k < NN) ? k : NN - 1;        // clamped addresses; deref guarded
    const int k2 = (k > 0) ? k - 1 : 0;
    const float* S1r = AP(float, OFF_S1) + ((size_t)hb * NN + k1) * NF;
    const float* S2r = AP(float, OFF_S2) + ((size_t)hb * NN + k2) * NF;
    __half* yr = AP(__half, OFF_Y) + ((size_t)hb * NN + row) * NF;
#pragma unroll
    for (int seg = 0; seg < 4; seg++) {
        const int f = seg * 128 + lane * 4;
        float4 a1 = make_float4(0.f, 0.f, 0.f, 0.f);
        float4 a2 = make_float4(0.f, 0.f, 0.f, 0.f);
        if (k < NN) a1 = *(const float4*)(S1r + f);
        if (k > 0)  a2 = *(const float4*)(S2r + f);
        __half2 p0, p1;
        p0.x = __float2half((a1.x + q * a2.x) * iz);
        p0.y = __float2half((a1.y + q * a2.y) * iz);
        p1.x = __float2half((a1.z + q * a2.z) * iz);
        p1.y = __float2half((a1.w + q * a2.w) * iz);
        *(__half2*)(yr + f) = p0;
        *(__half2*)(yr + f + 2) = p1;
    }
}

// ---------------------------------------------------------------------------
// Launch DAG:
//   s1: w2k -> s_comp -> sort_c [esort] -> attn_softmax [es1end]
//   0 : prep_x, prep_kT, bias_mean; (wait esort) scan_part -> scan_off ->
//       scan_write -> combine_y; (wait es1end) g2
// ---------------------------------------------------------------------------
extern "C" void kernel_launch(void* const* d_in, const int* in_sizes, int n_in,
                              void* d_out, int out_size)
{
    const float* x      = (const float*)d_in[0];
    const float* kern   = (const float*)d_in[1];
    const float* biases = (const float*)d_in[2];
    const float* aself  = (const float*)d_in[3];
    const float* aneigh = (const float*)d_in[4];
    float* out = (float*)d_out;

    static cudaStream_t s1 = nullptr;
    static cudaEvent_t efork = nullptr, esort = nullptr, es1end = nullptr;
    static bool attr_done = false;
    if (s1 == nullptr) {
        cudaStreamCreateWithFlags(&s1, cudaStreamNonBlocking);
        cudaEventCreateWithFlags(&efork, cudaEventDisableTiming);
        cudaEventCreateWithFlags(&esort, cudaEventDisableTiming);
        cudaEventCreateWithFlags(&es1end, cudaEventDisableTiming);
    }
    if (!attr_done) {
        cudaFuncSetAttribute(g2_tc, cudaFuncAttributeMaxDynamicSharedMemorySize, G_SMEM);
        cudaFuncSetAttribute(scan_write, cudaFuncAttributeMaxDynamicSharedMemorySize, SW_DSM);
        attr_done = true;
    }

    // Fork
    cudaEventRecord(efork, 0);
    cudaStreamWaitEvent(s1, efork, 0);

    // Side stream: logits chain + sort (gates scans), then exact softmax
    w2k<<<(NH * NF) / 8, 256, 0, s1>>>(kern, aself, aneigh);
    s_comp<<<(NB * NN) / 8, 256, 0, s1>>>(x);
    sort_c<<<NH * NB, 1024, 0, s1>>>();
    cudaEventRecord(esort, s1);
    attn_softmax<<<(NH * NB * NN) / 8, 256, 0, s1>>>(out);
    cudaEventRecord(es1end, s1);

    // Main stream: prep
    prep_x<<<(NB * NN * NF / 4) / 256, 256>>>(x);
    prep_kT<<<dim3(NFP / 32, NF / 32, NH), dim3(32, 8)>>>(kern);
    bias_mean<<<NFP / 256, 256>>>(biases);

    // Scan pipeline (needs prep_x + sort)
    cudaStreamWaitEvent(0, esort, 0);
    scan_part<<<dim3(NH * NB, 16), 256>>>();
    scan_off<<<NH * NB, 512>>>();
    scan_write<<<dim3(NH * NB, 16), 256, SW_DSM>>>();
    combine_y<<<dim3(NN / 8, NH * NB), 256>>>();

    // G2 (joins the side-stream tail for capture)
    cudaStreamWaitEvent(0, es1end, 0);
    g2_tc<<<dim3(NFP / 128, NN / 128, NB), 256, G_SMEM>>>(out);
}

// round 15
// speedup vs baseline: 1.3154x; 1.0943x over previous
#include <cuda_runtime.h>
#include <cuda_fp16.h>
#include <stdint.h>

#define NH 3
#define NB 16
#define NN 1024
#define NF 512
#define NFP 1024

// ---------------------------------------------------------------------------
// Scratch arena
// ---------------------------------------------------------------------------
#define OFF_XH    0ull            // x fp16 [b][n][f]          16 MB
#define OFF_KTH   16777216ull     // kernels^T fp16 [h][fp][f]  3 MB
#define OFF_Y     19922944ull     // y fp16 [hb][n][f]         48 MB
#define OFF_S1    70254592ull     // suffix sums fp16 [hb][idx][f]  48 MB
#define OFF_S2    170917888ull    // prefix sums fp16 [hb][idx][f]  48 MB
#define OFF_CP1   271581184ull    // chunk partials/offsets fp32 [hb][16][f]
#define OFF_CP2   273154048ull
#define OFF_CS    274726912ull    // sorted c
#define OFF_PERM  274923520ull
#define OFF_W1    275120128ull    // e^{c-M}
#define OFF_W2    275316736ull    // e^{0.2(c-M)}
#define OFF_Z1S   275513344ull
#define OFF_Z2P   275709952ull
#define OFF_MM    275906560ull    // per-hb max c
#define OFF_W2S   275906816ull
#define OFF_W2N   275912960ull
#define OFF_SS    275919104ull
#define OFF_SN    276115712ull
#define OFF_BM    276312320ull
#define ARENA_SZ  276316416ull

__device__ __align__(128) unsigned char g_arena[ARENA_SZ];
#define AP(T, off) ((T*)(g_arena + (off)))

// ---------------------------------------------------------------------------
// PTX helpers (base sm_103 target)
// ---------------------------------------------------------------------------
__device__ __forceinline__ uint32_t smem_u32(const void* p) {
    uint32_t a;
    asm("{ .reg .u64 t; cvta.to.shared.u64 t, %1; cvt.u32.u64 %0, t; }"
        : "=r"(a) : "l"(p));
    return a;
}
__device__ __forceinline__ void cpasync16(uint32_t s, const void* g) {
    asm volatile("cp.async.cg.shared.global [%0], [%1], 16;"
                 :: "r"(s), "l"(g) : "memory");
}
__device__ __forceinline__ void cp_commit() {
    asm volatile("cp.async.commit_group;" ::: "memory");
}
template <int N>
__device__ __forceinline__ void cp_wait() {
    asm volatile("cp.async.wait_group %0;" :: "n"(N) : "memory");
}
__device__ __forceinline__ void ldsm4(uint32_t* r, uint32_t a) {
    asm volatile("ldmatrix.sync.aligned.m8n8.x4.shared.b16 {%0,%1,%2,%3}, [%4];"
                 : "=r"(r[0]), "=r"(r[1]), "=r"(r[2]), "=r"(r[3]) : "r"(a));
}
__device__ __forceinline__ void mma16816(float* c, const uint32_t* a,
                                         const uint32_t* b) {
    asm volatile(
        "mma.sync.aligned.m16n8k16.row.col.f32.f16.f16.f32 "
        "{%0,%1,%2,%3}, {%4,%5,%6,%7}, {%8,%9}, {%0,%1,%2,%3};"
        : "+f"(c[0]), "+f"(c[1]), "+f"(c[2]), "+f"(c[3])
        : "r"(a[0]), "r"(a[1]), "r"(a[2]), "r"(a[3]), "r"(b[0]), "r"(b[1]));
}

// ---------------------------------------------------------------------------
// GEMM core (R5 config, proven): 128x128 CTA tile, kc=64, fp16 K-major.
// ---------------------------------------------------------------------------
#define GP_PITCH  144
#define G_TILE    18432
#define G_STAGE   36864
#define G_SMEM    110592

__device__ __forceinline__ void ld_stage(
    uint32_t st, int tid, const __half* A, const __half* B, int lda, int ldb)
{
#pragma unroll
    for (int it = 0; it < 4; it++) {
        const int idx = it * 256 + tid;
        const int row = idx >> 3, seg = idx & 7;
        const uint32_t so = row * GP_PITCH + seg * 16;
        cpasync16(st + so,          (const char*)(A + (size_t)row * lda) + seg * 16);
        cpasync16(st + G_TILE + so, (const char*)(B + (size_t)row * ldb) + seg * 16);
    }
    cp_commit();
}

template <int S, int KPH>
__device__ __forceinline__ void gemm_mma(
    const __half* A0, const __half* B0, size_t hstA, size_t hstB,
    int lda, int ldb, uint32_t sb, float acc[4][4][4],
    int wm, int wn, int lane, int tid)
{
#pragma unroll
    for (int mt = 0; mt < 4; mt++)
#pragma unroll
        for (int nt = 0; nt < 4; nt++)
#pragma unroll
            for (int q = 0; q < 4; q++) acc[mt][nt][q] = 0.f;

    ld_stage(sb,           tid, A0,      B0,      lda, ldb);
    ld_stage(sb + G_STAGE, tid, A0 + 64, B0 + 64, lda, ldb);

    for (int s = 0; s < S; s++) {
        if (s < S - 1) cp_wait<1>(); else cp_wait<0>();
        __syncthreads();
        const int sn = s + 2;
        if (sn < S) {
            const int hh = sn / KPH, kt = (sn % KPH) * 64;
            ld_stage(sb + (sn % 3) * G_STAGE, tid,
                     A0 + hh * hstA + kt, B0 + hh * hstB + kt, lda, ldb);
        }
        const uint32_t bu = sb + (s % 3) * G_STAGE;
        const uint32_t Ab = bu, Bb = bu + G_TILE;
#pragma unroll
        for (int ks = 0; ks < 4; ks++) {
            uint32_t bq[4][2];
            const int bcol = ks * 16 + (((lane >> 3) & 1) << 3);
            const int brow_in = ((lane >> 4) << 3) + (lane & 7);
#pragma unroll
            for (int p = 0; p < 2; p++) {
                uint32_t r[4];
                const int brow = wn * 32 + p * 16 + brow_in;
                ldsm4(r, Bb + (uint32_t)brow * GP_PITCH + bcol * 2);
                bq[2 * p][0] = r[0]; bq[2 * p][1] = r[1];
                bq[2 * p + 1][0] = r[2]; bq[2 * p + 1][1] = r[3];
            }
            const int arow = wm * 64 + (lane & 15);
            const int acol = ks * 16 + (lane >> 4) * 8;
#pragma unroll
            for (int mt = 0; mt < 4; mt++) {
                uint32_t aq[4];
                ldsm4(aq, Ab + (uint32_t)(arow + mt * 16) * GP_PITCH + acol * 2);
#pragma unroll
                for (int nt = 0; nt < 4; nt++)
                    mma16816(acc[mt][nt], aq, bq[nt]);
            }
        }
    }
}

// ---------------------------------------------------------------------------
// G2: out[b][node][fp] = (1/3) sum_h sum_f y[hb][node][f] * kT[h][fp][f] + bm
// ---------------------------------------------------------------------------
__global__ void __launch_bounds__(256, 2) g2_tc(float* __restrict__ out) {
    extern __shared__ char dynsm[];
    const int tid = threadIdx.x;
    const int w = tid >> 5, lane = tid & 31;
    const int wm = w & 1, wn = w >> 1;
    const int b = blockIdx.z;
    const int m0 = blockIdx.y * 128;   // node tile
    const int n0 = blockIdx.x * 128;   // fp tile

    const size_t hstA = (size_t)NB * NN * NF;
    const size_t hstB = (size_t)NFP * NF;
    const __half* A0 = AP(__half, OFF_Y)   + ((size_t)b * NN + m0) * NF;
    const __half* B0 = AP(__half, OFF_KTH) + (size_t)n0 * NF;

    float acc[4][4][4];
    gemm_mma<24, 8>(A0, B0, hstA, hstB, NF, NF, smem_u32(dynsm), acc, wm, wn, lane, tid);

    const float* bm = AP(float, OFF_BM);
    float* C = out + ((size_t)(NH * NB) + b) * NN * NN;
#pragma unroll
    for (int mt = 0; mt < 4; mt++)
#pragma unroll
        for (int nt = 0; nt < 4; nt++)
#pragma unroll
            for (int hf = 0; hf < 2; hf++) {
                const int row = m0 + wm * 64 + mt * 16 + (lane >> 2) + hf * 8;
                const int col = n0 + wn * 32 + nt * 8 + (lane & 3) * 2;
                float2 v;
                v.x = acc[mt][nt][hf * 2 + 0] * (1.f / 3.f) + bm[col + 0];
                v.y = acc[mt][nt][hf * 2 + 1] * (1.f / 3.f) + bm[col + 1];
                *(float2*)(C + (size_t)row * NN + col) = v;
            }
}

// ---------------------------------------------------------------------------
// Prep + logits chain
// ---------------------------------------------------------------------------
__global__ void prep_x(const float* __restrict__ x) {
    const size_t i = (size_t)blockIdx.x * 256 + threadIdx.x;
    float4 v = ((const float4*)x)[i];
    union { __half h[4]; uint2 u; } o;
    o.h[0] = __float2half(v.x); o.h[1] = __float2half(v.y);
    o.h[2] = __float2half(v.z); o.h[3] = __float2half(v.w);
    ((uint2*)AP(unsigned char, OFF_XH))[i] = o.u;
}

__global__ void prep_kT(const float* __restrict__ kern) {
    __shared__ float t[32][33];
    const int h = blockIdx.z;
    const int fp0 = blockIdx.x * 32, f0 = blockIdx.y * 32;
    const float* src = kern + (size_t)h * NF * NFP;
#pragma unroll
    for (int j = 0; j < 4; j++)
        t[threadIdx.y + j * 8][threadIdx.x] =
            src[(size_t)(f0 + threadIdx.y + j * 8) * NFP + fp0 + threadIdx.x];
    __syncthreads();
    __half* dst = AP(__half, OFF_KTH) + (size_t)h * NFP * NF;
#pragma unroll
    for (int j = 0; j < 4; j++) {
        float v = t[threadIdx.x][threadIdx.y + j * 8];
        dst[(size_t)(fp0 + threadIdx.y + j * 8) * NF + f0 + threadIdx.x] =
            __float2half(v);
    }
}

__global__ void w2k(const float* __restrict__ kern,
                    const float* __restrict__ as, const float* __restrict__ an) {
    const int gw = blockIdx.x * 8 + (threadIdx.x >> 5);
    const int lane = threadIdx.x & 31;
    const int h = gw >> 9, f = gw & 511;
    const float* row = kern + ((size_t)h * NF + f) * NFP;
    const float* a1 = as + (size_t)h * NFP;
    const float* a2 = an + (size_t)h * NFP;
    float s1 = 0.f, s2 = 0.f;
#pragma unroll
    for (int it = 0; it < 8; it++) {
        int k = it * 128 + lane * 4;
        float4 kv = *(const float4*)(row + k);
        float4 v1 = *(const float4*)(a1 + k);
        float4 v2 = *(const float4*)(a2 + k);
        s1 += kv.x * v1.x + kv.y * v1.y + kv.z * v1.z + kv.w * v1.w;
        s2 += kv.x * v2.x + kv.y * v2.y + kv.z * v2.z + kv.w * v2.w;
    }
#pragma unroll
    for (int o = 16; o > 0; o >>= 1) {
        s1 += __shfl_xor_sync(0xFFFFFFFFu, s1, o);
        s2 += __shfl_xor_sync(0xFFFFFFFFu, s2, o);
    }
    if (lane == 0) {
        AP(float, OFF_W2S)[(size_t)h * NF + f] = s1;
        AP(float, OFF_W2N)[(size_t)h * NF + f] = s2;
    }
}

__global__ void __launch_bounds__(256) s_comp(const float* __restrict__ x) {
    __shared__ float ws[NH * NF], wn_[NH * NF];
    for (int i = threadIdx.x; i < NH * NF; i += 256) {
        ws[i]  = AP(float, OFF_W2S)[i];
        wn_[i] = AP(float, OFF_W2N)[i];
    }
    __syncthreads();
    const int gw = blockIdx.x * 8 + (threadIdx.x >> 5);
    const int lane = threadIdx.x & 31;
    const int b = gw >> 10, n = gw & 1023;
    const float* xr = x + ((size_t)b * NN + n) * NF;
    float a[3] = {0.f, 0.f, 0.f}, c[3] = {0.f, 0.f, 0.f};
#pragma unroll
    for (int it = 0; it < 4; it++) {
        int f = it * 128 + lane * 4;
        float4 xv = *(const float4*)(xr + f);
#pragma unroll
        for (int h = 0; h < 3; h++) {
            float4 w = *(const float4*)&ws[h * NF + f];
            float4 u = *(const float4*)&wn_[h * NF + f];
            a[h] += xv.x * w.x + xv.y * w.y + xv.z * w.z + xv.w * w.w;
            c[h] += xv.x * u.x + xv.y * u.y + xv.z * u.z + xv.w * u.w;
        }
    }
#pragma unroll
    for (int h = 0; h < 3; h++) {
#pragma unroll
        for (int o = 16; o > 0; o >>= 1) {
            a[h] += __shfl_xor_sync(0xFFFFFFFFu, a[h], o);
            c[h] += __shfl_xor_sync(0xFFFFFFFFu, c[h], o);
        }
    }
    if (lane == 0) {
#pragma unroll
        for (int h = 0; h < 3; h++) {
            AP(float, OFF_SS)[(size_t)h * NB * NN + b * NN + n] = a[h];
            AP(float, OFF_SN)[(size_t)h * NB * NN + b * NN + n] = c[h];
        }
    }
}

// Exact fp32 row softmax -> d_out attn slices only (runs under g2).
__global__ void __launch_bounds__(256) attn_softmax(float* __restrict__ out) {
    __shared__ float c[NN];
    const int w    = threadIdx.x >> 5;
    const int lane = threadIdx.x & 31;
    const size_t r0 = (size_t)blockIdx.x * 8;
    const size_t hb = r0 >> 10;
    const float* cn = AP(float, OFF_SN) + hb * NN;
    for (int i = threadIdx.x; i < NN; i += 256) c[i] = cn[i];
    __syncthreads();

    const size_t r = r0 + w;
    const float a = AP(float, OFF_SS)[r];

    float ev[32];
    float m = -1e30f;
#pragma unroll
    for (int it = 0; it < 32; it++) {
        float t = a + c[it * 32 + lane];
        t = (t >= 0.f) ? t : 0.2f * t;
        ev[it] = t;
        m = fmaxf(m, t);
    }
#pragma unroll
    for (int o = 16; o > 0; o >>= 1) m = fmaxf(m, __shfl_xor_sync(0xFFFFFFFFu, m, o));
    float s = 0.f;
#pragma unroll
    for (int it = 0; it < 32; it++) {
        float e = __expf(ev[it] - m);
        ev[it] = e;
        s += e;
    }
#pragma unroll
    for (int o = 16; o > 0; o >>= 1) s += __shfl_xor_sync(0xFFFFFFFFu, s, o);
    const float inv = 1.f / s;

    float* orow = out + r * NN;
#pragma unroll
    for (int it = 0; it < 32; it++)
        orow[it * 32 + lane] = ev[it] * inv;
}

__global__ void bias_mean(const float* __restrict__ biases) {
    int k = blockIdx.x * 256 + threadIdx.x;
    AP(float, OFF_BM)[k] =
        (biases[k] + biases[NFP + k] + biases[2 * NFP + k]) * (1.f / 3.f);
}

// Trailing joiner: ties the side stream back into stream 0 after g2.
__global__ void joiner() {}

// ---------------------------------------------------------------------------
// sort_c (R8/R14-verified): bitonic sort of c per hb; emits perm, cs, w1, w2,
// scalar suffix/prefix sums z1s/z2p, and M.
// ---------------------------------------------------------------------------
__global__ void __launch_bounds__(1024) sort_c() {
    __shared__ float key[1024];
    __shared__ int   val[1024];
    __shared__ float buf[1024];
    const int hb = blockIdx.x, tid = threadIdx.x;
    key[tid] = AP(float, OFF_SN)[(size_t)hb * NN + tid];
    val[tid] = tid;
    __syncthreads();
    for (int ksz = 2; ksz <= 1024; ksz <<= 1)
        for (int j = ksz >> 1; j > 0; j >>= 1) {
            const int ixj = tid ^ j;
            if (ixj > tid) {
                const bool asc = ((tid & ksz) == 0);
                float a = key[tid], bb = key[ixj];
                if ((a > bb) == asc) {
                    key[tid] = bb; key[ixj] = a;
                    int tv = val[tid]; val[tid] = val[ixj]; val[ixj] = tv;
                }
            }
            __syncthreads();
        }
    const float M1 = key[1023];
    const float cv = key[tid];
    const float w1 = __expf(cv - M1);
    const float w2 = __expf(0.2f * (cv - M1));
    AP(float, OFF_CS)[(size_t)hb * NN + tid] = cv;
    AP(int,   OFF_PERM)[(size_t)hb * NN + tid] = val[tid];
    AP(float, OFF_W1)[(size_t)hb * NN + tid] = w1;
    AP(float, OFF_W2)[(size_t)hb * NN + tid] = w2;
    if (tid == 0) AP(float, OFF_MM)[hb] = M1;
    __syncthreads();

    buf[tid] = w2;                       // z2pre inclusive forward
    __syncthreads();
    for (int off = 1; off < 1024; off <<= 1) {
        float v = (tid >= off) ? buf[tid - off] : 0.f;
        __syncthreads();
        buf[tid] += v;
        __syncthreads();
    }
    AP(float, OFF_Z2P)[(size_t)hb * NN + tid] = buf[tid];
    __syncthreads();

    buf[1023 - tid] = w1;                // z1suf inclusive (reversed)
    __syncthreads();
    for (int off = 1; off < 1024; off <<= 1) {
        float v = (tid >= off) ? buf[tid - off] : 0.f;
        __syncthreads();
        buf[tid] += v;
        __syncthreads();
    }
    AP(float, OFF_Z1S)[(size_t)hb * NN + (1023 - tid)] = buf[tid];
}

// ---------------------------------------------------------------------------
// Hierarchical weighted scans of x rows in sorted order (per hb, 16 chunks of 64)
// ---------------------------------------------------------------------------
// Phase A: chunk totals T1/T2 per f.
__global__ void __launch_bounds__(256) scan_part() {
    __shared__ int   sp[64];
    __shared__ float sw1[64], sw2[64];
    const int hb = blockIdx.x, ch = blockIdx.y;
    const int b = hb & 15;
    const int t = threadIdx.x;            // f pair = 2t
    if (t < 64) {
        sp[t]  = AP(int,   OFF_PERM)[(size_t)hb * NN + ch * 64 + t];
        sw1[t] = AP(float, OFF_W1)[(size_t)hb * NN + ch * 64 + t];
        sw2[t] = AP(float, OFF_W2)[(size_t)hb * NN + ch * 64 + t];
    }
    __syncthreads();
    const __half* xb = AP(__half, OFF_XH) + (size_t)b * NN * NF;
    float2 a1 = make_float2(0.f, 0.f), a2 = make_float2(0.f, 0.f);
#pragma unroll 4
    for (int i = 0; i < 64; i++) {
        __half2 h = *(const __half2*)(xb + (size_t)sp[i] * NF + 2 * t);
        float2 f = __half22float2(h);
        a1.x += sw1[i] * f.x; a1.y += sw1[i] * f.y;
        a2.x += sw2[i] * f.x; a2.y += sw2[i] * f.y;
    }
    *(float2*)(AP(float, OFF_CP1) + ((size_t)hb * 16 + ch) * NF + 2 * t) = a1;
    *(float2*)(AP(float, OFF_CP2) + ((size_t)hb * 16 + ch) * NF + 2 * t) = a2;
}

// Phase B: in-place exclusive offsets (suffix for S1, prefix for S2).
__global__ void __launch_bounds__(512) scan_off() {
    const int hb = blockIdx.x;
    const int f = threadIdx.x;
    float* cp1 = AP(float, OFF_CP1) + (size_t)hb * 16 * NF + f;
    float* cp2 = AP(float, OFF_CP2) + (size_t)hb * 16 * NF + f;
    float run = 0.f;
    for (int c = 15; c >= 0; c--) {
        float v = cp1[(size_t)c * NF];
        cp1[(size_t)c * NF] = run;
        run += v;
    }
    run = 0.f;
    for (int c = 0; c < 16; c++) {
        float v = cp2[(size_t)c * NF];
        cp2[(size_t)c * NF] = run;
        run += v;
    }
}

// Phase C: full S1 (suffix) and S2 (prefix), fp16 storage; rows cached in smem.
#define SW_DSM 65536
__global__ void __launch_bounds__(256) scan_write() {
    extern __shared__ __half rows[];     // [64][512]
    __shared__ int   sp[64];
    __shared__ float sw1[64], sw2[64];
    const int hb = blockIdx.x, ch = blockIdx.y;
    const int b = hb & 15;
    const int t = threadIdx.x;            // f pair = 2t
    if (t < 64) {
        sp[t]  = AP(int,   OFF_PERM)[(size_t)hb * NN + ch * 64 + t];
        sw1[t] = AP(float, OFF_W1)[(size_t)hb * NN + ch * 64 + t];
        sw2[t] = AP(float, OFF_W2)[(size_t)hb * NN + ch * 64 + t];
    }
    __syncthreads();
    const __half* xb = AP(__half, OFF_XH) + (size_t)b * NN * NF;
#pragma unroll 4
    for (int i = 0; i < 64; i++)
        *(__half2*)(rows + i * NF + 2 * t) =
            *(const __half2*)(xb + (size_t)sp[i] * NF + 2 * t);
    __syncthreads();

    const size_t base = (size_t)hb * NN + ch * 64;
    float2 r1 = *(float2*)(AP(float, OFF_CP1) + ((size_t)hb * 16 + ch) * NF + 2 * t);
    for (int i = 63; i >= 0; i--) {
        float2 f = __half22float2(*(__half2*)(rows + i * NF + 2 * t));
        r1.x += sw1[i] * f.x; r1.y += sw1[i] * f.y;
        *(__half2*)(AP(__half, OFF_S1) + (base + i) * NF + 2 * t) =
            __floats2half2_rn(r1.x, r1.y);
    }
    float2 r2 = *(float2*)(AP(float, OFF_CP2) + ((size_t)hb * 16 + ch) * NF + 2 * t);
    for (int i = 0; i < 64; i++) {
        float2 f = __half22float2(*(__half2*)(rows + i * NF + 2 * t));
        r2.x += sw2[i] * f.x; r2.y += sw2[i] * f.y;
        *(__half2*)(AP(__half, OFF_S2) + (base + i) * NF + 2 * t) =
            __floats2half2_rn(r2.x, r2.y);
    }
}

// y[hb][row][:] = (S1[k] + q*S2[k-1]) / (z1s[k] + q*z2p[k-1]); fp16 out.
__global__ void __launch_bounds__(256) combine_y() {
    __shared__ float cs[NN];
    __shared__ int   sk[8];
    __shared__ float sq[8], siz[8];
    const int hb = blockIdx.y;
    const int r0 = blockIdx.x * 8;
    const int w = threadIdx.x >> 5, lane = threadIdx.x & 31;
    const float* csg = AP(float, OFF_CS) + (size_t)hb * NN;
    for (int i = threadIdx.x; i < NN; i += 256) cs[i] = csg[i];
    __syncthreads();

    const int row = r0 + w;
    const float s = AP(float, OFF_SS)[(size_t)hb * NN + row];
    if (lane == 0) {
        int lo = 0, hi = NN;
        while (lo < hi) {
            int mid = (lo + hi) >> 1;
            if (s + cs[mid] >= 0.f) hi = mid; else lo = mid + 1;
        }
        const float q = __expf(-0.8f * (s + AP(float, OFF_MM)[hb]));
        const float z1 = (lo < NN) ? AP(float, OFF_Z1S)[(size_t)hb * NN + lo] : 0.f;
        const float z2 = (lo > 0) ? AP(float, OFF_Z2P)[(size_t)hb * NN + lo - 1] : 0.f;
        sk[w] = lo; sq[w] = q; siz[w] = 1.f / (z1 + q * z2);
    }
    __syncwarp();
    const int k = sk[w];
    const float q = sq[w], iz = siz[w];
    const int k1 = (k < NN) ? k : NN - 1;        // clamped addresses; deref guarded
    const int k2 = (k > 0) ? k - 1 : 0;
    const __half* S1r = AP(__half, OFF_S1) + ((size_t)hb * NN + k1) * NF;
    const __half* S2r = AP(__half, OFF_S2) + ((size_t)hb * NN + k2) * NF;
    __half* yr = AP(__half, OFF_Y) + ((size_t)hb * NN + row) * NF;
#pragma unroll
    for (int seg = 0; seg < 4; seg++) {
        const int f = seg * 128 + lane * 4;
        float4 a1 = make_float4(0.f, 0.f, 0.f, 0.f);
        float4 a2 = make_float4(0.f, 0.f, 0.f, 0.f);
        if (k < NN) {
            float2 lo2 = __half22float2(*(const __half2*)(S1r + f));
            float2 hi2 = __half22float2(*(const __half2*)(S1r + f + 2));
            a1 = make_float4(lo2.x, lo2.y, hi2.x, hi2.y);
        }
        if (k > 0) {
            float2 lo2 = __half22float2(*(const __half2*)(S2r + f));
            float2 hi2 = __half22float2(*(const __half2*)(S2r + f + 2));
            a2 = make_float4(lo2.x, lo2.y, hi2.x, hi2.y);
        }
        __half2 p0, p1;
        p0.x = __float2half((a1.x + q * a2.x) * iz);
        p0.y = __float2half((a1.y + q * a2.y) * iz);
        p1.x = __float2half((a1.z + q * a2.z) * iz);
        p1.y = __float2half((a1.w + q * a2.w) * iz);
        *(__half2*)(yr + f) = p0;
        *(__half2*)(yr + f + 2) = p1;
    }
}

// ---------------------------------------------------------------------------
// Launch DAG:
//   s1: w2k -> s_comp -> sort_c [esort] ... (wait escan) attn_softmax [es1end]
//   0 : prep_x, prep_kT, bias_mean; (wait esort) scan_part -> scan_off ->
//       scan_write -> combine_y [escan] -> g2 -> (wait es1end) joiner
//   attn_softmax overlaps g2 (issue-bound vs DRAM-bound).
// ---------------------------------------------------------------------------
extern "C" void kernel_launch(void* const* d_in, const int* in_sizes, int n_in,
                              void* d_out, int out_size)
{
    const float* x      = (const float*)d_in[0];
    const float* kern   = (const float*)d_in[1];
    const float* biases = (const float*)d_in[2];
    const float* aself  = (const float*)d_in[3];
    const float* aneigh = (const float*)d_in[4];
    float* out = (float*)d_out;

    static cudaStream_t s1 = nullptr;
    static cudaEvent_t efork = nullptr, esort = nullptr;
    static cudaEvent_t escan = nullptr, es1end = nullptr;
    static bool attr_done = false;
    if (s1 == nullptr) {
        cudaStreamCreateWithFlags(&s1, cudaStreamNonBlocking);
        cudaEventCreateWithFlags(&efork, cudaEventDisableTiming);
        cudaEventCreateWithFlags(&esort, cudaEventDisableTiming);
        cudaEventCreateWithFlags(&escan, cudaEventDisableTiming);
        cudaEventCreateWithFlags(&es1end, cudaEventDisableTiming);
    }
    if (!attr_done) {
        cudaFuncSetAttribute(g2_tc, cudaFuncAttributeMaxDynamicSharedMemorySize, G_SMEM);
        cudaFuncSetAttribute(scan_write, cudaFuncAttributeMaxDynamicSharedMemorySize, SW_DSM);
        attr_done = true;
    }

    // Fork
    cudaEventRecord(efork, 0);
    cudaStreamWaitEvent(s1, efork, 0);

    // Side stream: logits chain + sort (gates scans)
    w2k<<<(NH * NF) / 8, 256, 0, s1>>>(kern, aself, aneigh);
    s_comp<<<(NB * NN) / 8, 256, 0, s1>>>(x);
    sort_c<<<NH * NB, 1024, 0, s1>>>();
    cudaEventRecord(esort, s1);

    // Main stream: prep
    prep_x<<<(NB * NN * NF / 4) / 256, 256>>>(x);
    prep_kT<<<dim3(NFP / 32, NF / 32, NH), dim3(32, 8)>>>(kern);
    bias_mean<<<NFP / 256, 256>>>(biases);

    // Scan pipeline (needs prep_x + sort)
    cudaStreamWaitEvent(0, esort, 0);
    scan_part<<<dim3(NH * NB, 16), 256>>>();
    scan_off<<<NH * NB, 512>>>();
    scan_write<<<dim3(NH * NB, 16), 256, SW_DSM>>>();
    combine_y<<<dim3(NN / 8, NH * NB), 256>>>();
    cudaEventRecord(escan, 0);

    // Softmax overlaps g2 on the side stream (DRAM-bound under issue-bound GEMM)
    cudaStreamWaitEvent(s1, escan, 0);
    attn_softmax<<<(NH * NB * NN) / 8, 256, 0, s1>>>(out);
    cudaEventRecord(es1end, s1);

    // G2, then join the side-stream tail for capture
    g2_tc<<<dim3(NFP / 128, NN / 128, NB), 256, G_SMEM>>>(out);
    cudaStreamWaitEvent(0, es1end, 0);
    joiner<<<1, 1>>>();
}